// round 11
// baseline (speedup 1.0000x reference)
#include <cuda_runtime.h>
#include <cuda_bf16.h>

#define NN    100000
#define EE    3200000
#define IN_C  128
#define HID   16
#define OUT_C 64

// Scratch (allocation-free rule: __device__ globals). float4 -> 16B aligned.
__device__ float4 g_h1[NN * 4];   // h1, then reused for t1 = relu(a1+b1)
__device__ float4 g_a1[NN * 4];   // layer-1 aggregation accumulator
__device__ float4 g_a2[NN * 4];   // layer-2 aggregation accumulator (pre-W2)
__device__ float  g_dinv[NN];     // deg, then dinv
__device__ int    g_is64;         // edge_index dtype: 1 = int64, 0 = int32

// Scalar global reduction via asm: cannot be fused into vector RED by ptxas.
__device__ __forceinline__ void red_add_f32(float* addr, float v) {
    asm volatile("red.global.add.f32 [%0], %1;" :: "l"(addr), "f"(v) : "memory");
}

// Load edge index element `pos` under either storage dtype.
__device__ __forceinline__ int load_idx(const void* ei, size_t pos, int is64) {
    if (is64) return (int)((const long long*)ei)[pos];
    return ((const int*)ei)[pos];
}

// ---------------------------------------------------------------------------
// Detect edge_index storage dtype. int64 little-endian: odd 32-bit words are
// high words of values < 2^31 -> all zero. int32: odd words are edge ids.
__global__ void k_probe(const int* __restrict__ ei32) {
    if (threadIdx.x == 0 && blockIdx.x == 0) {
        int is64 = 1;
        for (int i = 0; i < 1024; i++) {
            if (ei32[2 * i + 1] != 0) { is64 = 0; break; }
        }
        g_is64 = is64;
    }
}

// ---------------------------------------------------------------------------
__global__ void k_init_deg() {
    int i = blockIdx.x * blockDim.x + threadIdx.x;
    if (i < NN) g_dinv[i] = 1.0f;   // self-loop contributes 1 to degree
}

__global__ void k_count(const void* __restrict__ ei) {
    int e = blockIdx.x * blockDim.x + threadIdx.x;
    if (e >= EE) return;
    int is64 = g_is64;
    int c = load_idx(ei, (size_t)EE + e, is64);   // col = target
    if ((unsigned)c >= NN) return;                // safety: never trap
    red_add_f32(&g_dinv[c], 1.0f);
}

__global__ void k_rsqrt() {
    int i = blockIdx.x * blockDim.x + threadIdx.x;
    if (i < NN) g_dinv[i] = rsqrtf(g_dinv[i]);
}

// ---------------------------------------------------------------------------
// h1 = x @ W1 ; a1 = h1 * dinv^2  (self-loop term pre-seeded into accumulator)
__global__ void k_gemm1(const float* __restrict__ x, const float* __restrict__ W1) {
    __shared__ float sW[IN_C * HID];
    for (int i = threadIdx.x; i < IN_C * HID; i += blockDim.x) sW[i] = W1[i];
    __syncthreads();

    int node = blockIdx.x * blockDim.x + threadIdx.x;
    if (node >= NN) return;

    float acc[HID];
#pragma unroll
    for (int h = 0; h < HID; h++) acc[h] = 0.0f;

    const float4* xr = (const float4*)(x + (size_t)node * IN_C);
#pragma unroll 4
    for (int k4 = 0; k4 < IN_C / 4; k4++) {
        float4 v = xr[k4];
        int k = k4 * 4;
#pragma unroll
        for (int h = 0; h < HID; h++) {
            acc[h] += v.x * sW[(k + 0) * HID + h]
                    + v.y * sW[(k + 1) * HID + h]
                    + v.z * sW[(k + 2) * HID + h]
                    + v.w * sW[(k + 3) * HID + h];
        }
    }

    float di = g_dinv[node];
    float sl = di * di;
#pragma unroll
    for (int q = 0; q < 4; q++) {
        float4 hv = make_float4(acc[4*q+0], acc[4*q+1], acc[4*q+2], acc[4*q+3]);
        g_h1[(size_t)node * 4 + q] = hv;
        g_a1[(size_t)node * 4 + q] = make_float4(hv.x*sl, hv.y*sl, hv.z*sl, hv.w*sl);
    }
}

// ---------------------------------------------------------------------------
// Edge aggregation: dst[col] += src[row] * dinv[row]*dinv[col]
// 4 threads per edge, each handles one float4 chunk of the 16-dim feature.
template <int LAYER>
__global__ void k_agg(const void* __restrict__ ei) {
    int tid = blockIdx.x * blockDim.x + threadIdx.x;
    int e = tid >> 2;
    if (e >= EE) return;
    int c = tid & 3;

    int is64 = g_is64;
    int r = load_idx(ei, e, is64);                // row = source
    int t = load_idx(ei, (size_t)EE + e, is64);   // col = target
    if ((unsigned)r >= NN || (unsigned)t >= NN) return;   // safety: never trap

    float nrm = g_dinv[r] * g_dinv[t];

    float4 v = g_h1[(size_t)r * 4 + c];
    float* dst = (float*)((LAYER == 0 ? g_a1 : g_a2) + (size_t)t * 4 + c);
    red_add_f32(dst + 0, v.x * nrm);
    red_add_f32(dst + 1, v.y * nrm);
    red_add_f32(dst + 2, v.z * nrm);
    red_add_f32(dst + 3, v.w * nrm);
}

// ---------------------------------------------------------------------------
// t1 = relu(a1 + b1) -> g_h1 ; a2 = t1 * dinv^2 (self-loop pre-seed)
__global__ void k_relu(const float* __restrict__ b1) {
    int i = blockIdx.x * blockDim.x + threadIdx.x;
    if (i >= NN * 4) return;
    int node = i >> 2;
    int hb = (i & 3) * 4;

    float4 t = g_a1[i];
    t.x = fmaxf(t.x + b1[hb + 0], 0.0f);
    t.y = fmaxf(t.y + b1[hb + 1], 0.0f);
    t.z = fmaxf(t.z + b1[hb + 2], 0.0f);
    t.w = fmaxf(t.w + b1[hb + 3], 0.0f);
    g_h1[i] = t;

    float di = g_dinv[node];
    float sl = di * di;
    g_a2[i] = make_float4(t.x * sl, t.y * sl, t.z * sl, t.w * sl);
}

// ---------------------------------------------------------------------------
// out = a2 @ W2 + b2   (a2: [N,16], W2: [16,64])
__global__ void k_gemm2(const float* __restrict__ W2, const float* __restrict__ b2,
                        float* __restrict__ out) {
    __shared__ float sW[HID * OUT_C];
    __shared__ float sb[OUT_C];
    for (int i = threadIdx.x; i < HID * OUT_C; i += blockDim.x) sW[i] = W2[i];
    if (threadIdx.x < OUT_C) sb[threadIdx.x] = b2[threadIdx.x];
    __syncthreads();

    int idx = blockIdx.x * blockDim.x + threadIdx.x;
    if (idx >= NN * OUT_C) return;
    int node = idx >> 6;
    int oc = idx & (OUT_C - 1);

    const float* ar = (const float*)(g_a2 + (size_t)node * 4);
    float acc = sb[oc];
#pragma unroll
    for (int k = 0; k < HID; k++) acc += ar[k] * sW[k * OUT_C + oc];
    out[idx] = acc;
}

// ---------------------------------------------------------------------------
extern "C" void kernel_launch(void* const* d_in, const int* in_sizes, int n_in,
                              void* d_out, int out_size) {
    const float* x  = (const float*)d_in[0];
    const void*  ei = d_in[1];                 // int32 or int64 -> probed on device
    const float* W1 = (const float*)d_in[2];
    const float* b1 = (const float*)d_in[3];
    const float* W2 = (const float*)d_in[4];
    const float* b2 = (const float*)d_in[5];
    float*       out = (float*)d_out;

    const int T = 256;

    k_probe<<<1, 32>>>((const int*)ei);
    k_init_deg<<<(NN + T - 1) / T, T>>>();
    k_count<<<(EE + T - 1) / T, T>>>(ei);
    k_rsqrt<<<(NN + T - 1) / T, T>>>();

    k_gemm1<<<(NN + 127) / 128, 128>>>(x, W1);
    k_agg<0><<<(EE * 4 + T - 1) / T, T>>>(ei);

    k_relu<<<(NN * 4 + T - 1) / T, T>>>(b1);
    k_agg<1><<<(EE * 4 + T - 1) / T, T>>>(ei);

    k_gemm2<<<(NN * OUT_C + T - 1) / T, T>>>(W2, b2, out);
}

// round 17
// speedup vs baseline: 1.8157x; 1.8157x over previous
#include <cuda_runtime.h>
#include <cuda_bf16.h>

#define NN    100000
#define EE    3200000
#define IN_C  128
#define HID   16
#define OUT_C 64
#define SCAN_BS 1024
#define SCAN_NB ((NN + SCAN_BS - 1) / SCAN_BS)   // 98

// ---- scratch (__device__ globals; no allocs) ------------------------------
__device__ int    g_row[EE];        // converted int32 sources
__device__ int    g_col[EE];        // converted int32 targets
__device__ int    g_srclist[EE];    // CSR source lists (scatter output)
__device__ int    g_deg[NN];        // in-degree histogram
__device__ int    g_off[NN + 1];    // CSR offsets
__device__ int    g_cur[NN];        // scatter cursors
__device__ int    g_bsum[SCAN_NB];  // block sums for scan
__device__ float  g_dinv[NN];       // rsqrt(deg+1)
__device__ float4 g_hs1[NN * 4];    // dinv * (x@W1)
__device__ float4 g_hs2[NN * 4];    // dinv * relu(agg1 + b1)
__device__ float4 g_a2[NN * 4];     // layer-2 aggregated (pre-W2)
__device__ int    g_is64;           // edge_index dtype flag

__device__ __forceinline__ int load_idx(const void* ei, size_t pos, int is64) {
    if (is64) return (int)((const long long*)ei)[pos];
    return ((const int*)ei)[pos];
}

// ---------------------------------------------------------------------------
// Dtype probe: int64 little-endian storage -> odd 32-bit words all zero.
__global__ void k_probe(const int* __restrict__ ei32) {
    if (threadIdx.x == 0 && blockIdx.x == 0) {
        int is64 = 1;
        for (int i = 0; i < 1024; i++)
            if (ei32[2 * i + 1] != 0) { is64 = 0; break; }
        g_is64 = is64;
    }
}

__global__ void k_zero_deg() {
    int i = blockIdx.x * blockDim.x + threadIdx.x;
    if (i < NN) g_deg[i] = 0;
}

// Convert edge_index to int32 and build in-degree histogram.
__global__ void k_convert_count(const void* __restrict__ ei) {
    int e = blockIdx.x * blockDim.x + threadIdx.x;
    if (e >= EE) return;
    int is64 = g_is64;
    int r = load_idx(ei, e, is64);
    int t = load_idx(ei, (size_t)EE + e, is64);
    if ((unsigned)r >= NN) r = 0;   // safety (never triggers on valid data)
    if ((unsigned)t >= NN) t = 0;
    g_row[e] = r;
    g_col[e] = t;
    atomicAdd(&g_deg[t], 1);
}

// ---- 2-level exclusive scan of g_deg -> g_off -----------------------------
__global__ void k_scan1() {
    __shared__ int s[SCAN_BS];
    int i = blockIdx.x * SCAN_BS + threadIdx.x;
    int v = (i < NN) ? g_deg[i] : 0;
    s[threadIdx.x] = v;
    __syncthreads();
#pragma unroll
    for (int o = 1; o < SCAN_BS; o <<= 1) {
        int u = (threadIdx.x >= o) ? s[threadIdx.x - o] : 0;
        __syncthreads();
        s[threadIdx.x] += u;
        __syncthreads();
    }
    if (i <= NN) g_off[i] = s[threadIdx.x] - v;        // exclusive
    if (threadIdx.x == SCAN_BS - 1) g_bsum[blockIdx.x] = s[threadIdx.x];
}

__global__ void k_scan2() {
    __shared__ int s[128];
    int t = threadIdx.x;
    int v = (t < SCAN_NB) ? g_bsum[t] : 0;
    s[t] = v;
    __syncthreads();
#pragma unroll
    for (int o = 1; o < 128; o <<= 1) {
        int u = (t >= o) ? s[t - o] : 0;
        __syncthreads();
        s[t] += u;
        __syncthreads();
    }
    if (t < SCAN_NB) g_bsum[t] = s[t] - v;             // exclusive block offsets
}

// Add block offsets; init cursors; compute dinv; set sentinel.
__global__ void k_scan3() {
    int i = blockIdx.x * blockDim.x + threadIdx.x;
    if (i < NN) {
        int off = g_off[i] + g_bsum[i / SCAN_BS];
        g_off[i] = off;
        g_cur[i] = off;
        g_dinv[i] = rsqrtf((float)g_deg[i] + 1.0f);
    }
    if (i == 0) g_off[NN] = EE;
}

// Scatter sources into CSR lists. Reads g_row/g_col, writes ONLY g_srclist
// (each slot written exactly once) -> race-free.
__global__ void k_scatter() {
    int e = blockIdx.x * blockDim.x + threadIdx.x;
    if (e >= EE) return;
    int t = g_col[e];
    int pos = atomicAdd(&g_cur[t], 1);
    g_srclist[pos] = g_row[e];
}

// ---------------------------------------------------------------------------
// hs1 = dinv * (x @ W1)
__global__ void k_gemm1(const float* __restrict__ x, const float* __restrict__ W1) {
    __shared__ float sW[IN_C * HID];
    for (int i = threadIdx.x; i < IN_C * HID; i += blockDim.x) sW[i] = W1[i];
    __syncthreads();

    int node = blockIdx.x * blockDim.x + threadIdx.x;
    if (node >= NN) return;

    float acc[HID];
#pragma unroll
    for (int h = 0; h < HID; h++) acc[h] = 0.0f;

    const float4* xr = (const float4*)(x + (size_t)node * IN_C);
#pragma unroll 4
    for (int k4 = 0; k4 < IN_C / 4; k4++) {
        float4 v = xr[k4];
        int k = k4 * 4;
#pragma unroll
        for (int h = 0; h < HID; h++) {
            acc[h] += v.x * sW[(k + 0) * HID + h]
                    + v.y * sW[(k + 1) * HID + h]
                    + v.z * sW[(k + 2) * HID + h]
                    + v.w * sW[(k + 3) * HID + h];
        }
    }

    float di = g_dinv[node];
#pragma unroll
    for (int q = 0; q < 4; q++)
        g_hs1[(size_t)node * 4 + q] = make_float4(acc[4*q+0]*di, acc[4*q+1]*di,
                                                  acc[4*q+2]*di, acc[4*q+3]*di);
}

// ---------------------------------------------------------------------------
// Gather aggregation: 16 threads per node, thread owns feature f.
// acc = hs[node] (self loop) + sum over CSR in-edges of hs[src].
// LAYER 0: epilogue relu(di*acc + b1)*di -> hs2.  LAYER 1: di*acc -> a2.
template <int LAYER>
__global__ void k_gather(const float* __restrict__ b1) {
    int gid = blockIdx.x * blockDim.x + threadIdx.x;
    int node = gid >> 4;
    if (node >= NN) return;
    int f = gid & 15;

    const float* hs = (const float*)(LAYER == 0 ? g_hs1 : g_hs2);
    const int* src = g_srclist;

    int beg = g_off[node], end = g_off[node + 1];
    float acc = hs[(node << 4) + f];      // self loop term

    int j = beg;
    for (; j + 4 <= end; j += 4) {
        int r0 = src[j], r1 = src[j+1], r2 = src[j+2], r3 = src[j+3];
        acc += hs[(r0 << 4) + f];
        acc += hs[(r1 << 4) + f];
        acc += hs[(r2 << 4) + f];
        acc += hs[(r3 << 4) + f];
    }
    for (; j < end; j++) acc += hs[(src[j] << 4) + f];

    float di = g_dinv[node];
    if (LAYER == 0) {
        float t1 = fmaxf(di * acc + b1[f], 0.0f);
        ((float*)g_hs2)[(node << 4) + f] = t1 * di;
    } else {
        ((float*)g_a2)[(node << 4) + f] = di * acc;
    }
}

// ---------------------------------------------------------------------------
// out = a2 @ W2 + b2
__global__ void k_gemm2(const float* __restrict__ W2, const float* __restrict__ b2,
                        float* __restrict__ out) {
    __shared__ float sW[HID * OUT_C];
    __shared__ float sb[OUT_C];
    for (int i = threadIdx.x; i < HID * OUT_C; i += blockDim.x) sW[i] = W2[i];
    if (threadIdx.x < OUT_C) sb[threadIdx.x] = b2[threadIdx.x];
    __syncthreads();

    int idx = blockIdx.x * blockDim.x + threadIdx.x;
    if (idx >= NN * OUT_C) return;
    int node = idx >> 6;
    int oc = idx & (OUT_C - 1);

    const float* ar = (const float*)(g_a2 + (size_t)node * 4);
    float acc = sb[oc];
#pragma unroll
    for (int k = 0; k < HID; k++) acc += ar[k] * sW[k * OUT_C + oc];
    out[idx] = acc;
}

// ---------------------------------------------------------------------------
extern "C" void kernel_launch(void* const* d_in, const int* in_sizes, int n_in,
                              void* d_out, int out_size) {
    const float* x  = (const float*)d_in[0];
    const void*  ei = d_in[1];
    const float* W1 = (const float*)d_in[2];
    const float* b1 = (const float*)d_in[3];
    const float* W2 = (const float*)d_in[4];
    const float* b2 = (const float*)d_in[5];
    float*       out = (float*)d_out;

    const int T = 256;

    k_probe<<<1, 32>>>((const int*)ei);
    k_zero_deg<<<(NN + T - 1) / T, T>>>();
    k_convert_count<<<(EE + T - 1) / T, T>>>(ei);

    k_scan1<<<SCAN_NB, SCAN_BS>>>();
    k_scan2<<<1, 128>>>();
    k_scan3<<<(NN + T - 1) / T, T>>>();
    k_scatter<<<(EE + T - 1) / T, T>>>();

    k_gemm1<<<(NN + 127) / 128, 128>>>(x, W1);
    k_gather<0><<<(NN * 16 + T - 1) / T, T>>>(b1);
    k_gather<1><<<(NN * 16 + T - 1) / T, T>>>(b1);
    k_gemm2<<<(NN * OUT_C + T - 1) / T, T>>>(W2, b2, out);
}